// round 13
// baseline (speedup 1.0000x reference)
#include <cuda_runtime.h>
#include <cuda_bf16.h>
#include <cuda_fp16.h>
#include <mma.h>

using namespace nvcuda;

constexpr int kNB = 2;     // batch
constexpr int kC  = 256;   // channels
constexpr int kCK = 32;    // key channels
constexpr int kL  = 4096;  // T*H*W
constexpr int kD  = 288;   // stacked output channels (32 k + 256 v)

// ---------------- scratch (static __device__ — no allocations allowed) ----------------
__device__ float g_Wp[2][kD][kC];            // packed weights per side (fp32, k-proj uses rows 0..31)
__device__ float g_bp[2][kD];                // packed bias per side
__device__ __half g_Wvh[2][kC][kC];          // v-weights fp16 [d][c]
__device__ float g_k[2][kNB][kCK][kL];       // k1 (side 0), k2 (side 1)
__device__ __nv_bfloat16 g_vh[2][kNB][kC][kL];        // scaled v, bf16 (written by proj_v epilogue)
__device__ __nv_bfloat16 g_Eh[(size_t)kNB * kL * kL]; // exp(cor), bf16 (64 MB)
__device__ float g_rs[kNB][kL];              // row sums of E -> inverted in place
__device__ float g_cs[kNB][kL];              // col sums of E -> inverted in place

// FFMA-only exp (avoids MUFU bottleneck: ~33M evals)
__device__ __forceinline__ float fast_exp(float x) {
    x = fminf(fmaxf(x, -80.0f), 80.0f);
    float y = x * 1.44269504088896341f;  // x * log2(e)
    float n = rintf(y);
    float f = y - n;
    float p =        1.3333558e-3f;
    p = fmaf(p, f,   9.6181291e-3f);
    p = fmaf(p, f,   5.5504110e-2f);
    p = fmaf(p, f,   2.4022652e-1f);
    p = fmaf(p, f,   6.9314718e-1f);
    p = fmaf(p, f,   1.0f);
    float s = __int_as_float(((int)n + 127) << 23);
    return p * s;
}

__device__ __forceinline__ void cp_async16(void* sdst, const void* gsrc) {
    unsigned saddr = (unsigned)__cvta_generic_to_shared(sdst);
    asm volatile("cp.async.cg.shared.global [%0], [%1], 16;\n" :: "r"(saddr), "l"(gsrc));
}
#define CP_ASYNC_COMMIT() asm volatile("cp.async.commit_group;\n" ::: "memory")
#define CP_ASYNC_WAIT2()  asm volatile("cp.async.wait_group 2;\n" ::: "memory")

// ---------------- kernel 1: pack weights + fp16 v-weights ----------------
__global__ void pack_w(const float* __restrict__ Wk1, const float* __restrict__ bk1,
                       const float* __restrict__ Wk2, const float* __restrict__ bk2,
                       const float* __restrict__ Wv1, const float* __restrict__ bv1,
                       const float* __restrict__ Wv2, const float* __restrict__ bv2) {
    int i = blockIdx.x * blockDim.x + threadIdx.x;
    if (i < kD * kC) {
        int d = i / kC, c = i % kC;
        g_Wp[0][d][c] = (d < kCK) ? Wk1[d * kC + c] : Wv1[(d - kCK) * kC + c];
        g_Wp[1][d][c] = (d < kCK) ? Wk2[d * kC + c] : Wv2[(d - kCK) * kC + c];
    }
    if (i < kC * kC) {
        int d = i >> 8, c = i & 255;
        g_Wvh[0][d][c] = __float2half_rn(Wv1[i]);
        g_Wvh[1][d][c] = __float2half_rn(Wv2[i]);
    }
    if (i < kD) {
        g_bp[0][i] = (i < kCK) ? bk1[i] : bv1[i - kCK];
        g_bp[1][i] = (i < kCK) ? bk2[i] : bv2[i - kCK];
    }
}

__global__ void zero_stats() {
    int i = blockIdx.x * blockDim.x + threadIdx.x;
    if (i < kNB * kL) {
        (&g_rs[0][0])[i] = 0.0f;
        (&g_cs[0][0])[i] = 0.0f;
    }
}

// ---------------- kernel 2a: k projection (fp32 SIMT, tiny: 0.27 GF) ----------------
__global__ void __launch_bounds__(256) proj_k(const float* __restrict__ x1,
                                              const float* __restrict__ x2) {
    const int side = blockIdx.z >> 1;
    const int n    = blockIdx.z & 1;
    const float* x = (side ? x2 : x1) + (size_t)n * kC * kL;
    const int l0 = blockIdx.x * 128;

    __shared__ float Ws[256][32];   // [k][d]
    __shared__ float Xs[16][128];

    const int tid = threadIdx.x;
    const int d  = tid & 31;
    const int lg = tid >> 5;

    for (int i = tid; i < 256 * 32; i += 256) {
        int k = i >> 5, dd = i & 31;
        Ws[k][dd] = g_Wp[side][dd][k];
    }

    float acc[16] = {};
    for (int kb = 0; kb < kC; kb += 16) {
        __syncthreads();
        for (int i = tid; i < 512; i += 256) {
            int k = i >> 5, g4 = (i & 31) << 2;
            *(float4*)&Xs[k][g4] = *(const float4*)&x[(size_t)(kb + k) * kL + l0 + g4];
        }
        __syncthreads();
        #pragma unroll
        for (int k = 0; k < 16; k++) {
            float w = Ws[kb + k][d];
            float4 v0 = *(float4*)&Xs[k][lg * 16];
            float4 v1 = *(float4*)&Xs[k][lg * 16 + 4];
            float4 v2 = *(float4*)&Xs[k][lg * 16 + 8];
            float4 v3 = *(float4*)&Xs[k][lg * 16 + 12];
            acc[0]  = fmaf(w, v0.x, acc[0]);  acc[1]  = fmaf(w, v0.y, acc[1]);
            acc[2]  = fmaf(w, v0.z, acc[2]);  acc[3]  = fmaf(w, v0.w, acc[3]);
            acc[4]  = fmaf(w, v1.x, acc[4]);  acc[5]  = fmaf(w, v1.y, acc[5]);
            acc[6]  = fmaf(w, v1.z, acc[6]);  acc[7]  = fmaf(w, v1.w, acc[7]);
            acc[8]  = fmaf(w, v2.x, acc[8]);  acc[9]  = fmaf(w, v2.y, acc[9]);
            acc[10] = fmaf(w, v2.z, acc[10]); acc[11] = fmaf(w, v2.w, acc[11]);
            acc[12] = fmaf(w, v3.x, acc[12]); acc[13] = fmaf(w, v3.y, acc[13]);
            acc[14] = fmaf(w, v3.z, acc[14]); acc[15] = fmaf(w, v3.w, acc[15]);
        }
    }
    float bias = g_bp[side][d];
    #pragma unroll
    for (int j = 0; j < 16; j++)
        g_k[side][n][d][l0 + lg * 16 + j] = acc[j] + bias;
}

// ---------------- kernel 3: cor = k1^T k2 via fp16 wmma, E=bf16(exp), fused sums ----------------
constexpr int kCorSmemBytes = 128 * 136 * 4;  // 69632 (stage dominates; half tiles overlap)

__global__ void __launch_bounds__(256) cor_kernel() {
    extern __shared__ float csm[];
    __half* hA = (__half*)csm;            // 32 x 136 halves ([k][l])
    __half* hB = hA + 32 * 136;           // 32 x 136 halves ([k][m])
    float* stage = csm;                   // 128 x 136 fp32, reused after mma

    const int n  = blockIdx.z;
    const int l0 = blockIdx.y * 128;
    const int m0 = blockIdx.x * 128;
    const int tid = threadIdx.x;
    const int warp = tid >> 5;
    const int wm = warp & 1, wn = warp >> 1;

    const float* k1 = &g_k[0][n][0][0];
    const float* k2 = &g_k[1][n][0][0];

    for (int i4 = tid; i4 < 1024; i4 += 256) {
        int k = i4 >> 5, j4 = (i4 & 31) << 2;
        float4 a = *(const float4*)&k1[(size_t)k * kL + l0 + j4];
        float4 b = *(const float4*)&k2[(size_t)k * kL + m0 + j4];
        __half2 a0 = __floats2half2_rn(a.x, a.y), a1 = __floats2half2_rn(a.z, a.w);
        __half2 b0 = __floats2half2_rn(b.x, b.y), b1 = __floats2half2_rn(b.z, b.w);
        uint2 ua, ub;
        ua.x = *(unsigned*)&a0; ua.y = *(unsigned*)&a1;
        ub.x = *(unsigned*)&b0; ub.y = *(unsigned*)&b1;
        *(uint2*)&hA[k * 136 + j4] = ua;
        *(uint2*)&hB[k * 136 + j4] = ub;
    }
    __syncthreads();

    wmma::fragment<wmma::accumulator, 16, 16, 16, float> acc[4][2];
    #pragma unroll
    for (int mi = 0; mi < 4; mi++)
        #pragma unroll
        for (int ni = 0; ni < 2; ni++)
            wmma::fill_fragment(acc[mi][ni], 0.0f);

    #pragma unroll
    for (int kk = 0; kk < 2; kk++) {
        wmma::fragment<wmma::matrix_a, 16, 16, 16, __half, wmma::col_major> af[4];
        wmma::fragment<wmma::matrix_b, 16, 16, 16, __half, wmma::row_major> bf[2];
        #pragma unroll
        for (int mi = 0; mi < 4; mi++)
            wmma::load_matrix_sync(af[mi], hA + (kk * 16) * 136 + wm * 64 + mi * 16, 136);
        #pragma unroll
        for (int ni = 0; ni < 2; ni++)
            wmma::load_matrix_sync(bf[ni], hB + (kk * 16) * 136 + wn * 32 + ni * 16, 136);
        #pragma unroll
        for (int mi = 0; mi < 4; mi++)
            #pragma unroll
            for (int ni = 0; ni < 2; ni++)
                wmma::mma_sync(acc[mi][ni], af[mi], bf[ni], acc[mi][ni]);
    }

    __syncthreads();  // done reading tiles; stage overwrites them
    #pragma unroll
    for (int mi = 0; mi < 4; mi++)
        #pragma unroll
        for (int ni = 0; ni < 2; ni++)
            wmma::store_matrix_sync(stage + (wm * 64 + mi * 16) * 136 + wn * 32 + ni * 16,
                                    acc[mi][ni], 136, wmma::mem_row_major);
    __syncthreads();

    // Phase A: exp + bf16 write + row sums; exp'd values written back to stage
    {
        const int r  = tid >> 1;
        const int ch = (tid & 1) << 6;  // 0 or 64
        float* srow = stage + r * 136 + ch;
        float rsum = 0.0f;
        size_t goff = (size_t)n * kL * kL + (size_t)(l0 + r) * kL + m0 + ch;
        #pragma unroll
        for (int j0 = 0; j0 < 64; j0 += 8) {
            float4 v0 = *(float4*)&srow[j0];
            float4 v1 = *(float4*)&srow[j0 + 4];
            __nv_bfloat162 b0 = __floats2bfloat162_rn(fast_exp(v0.x), fast_exp(v0.y));
            __nv_bfloat162 b1 = __floats2bfloat162_rn(fast_exp(v0.z), fast_exp(v0.w));
            __nv_bfloat162 b2 = __floats2bfloat162_rn(fast_exp(v1.x), fast_exp(v1.y));
            __nv_bfloat162 b3 = __floats2bfloat162_rn(fast_exp(v1.z), fast_exp(v1.w));
            float2 f0 = __bfloat1622float2(b0), f1 = __bfloat1622float2(b1);
            float2 f2 = __bfloat1622float2(b2), f3 = __bfloat1622float2(b3);
            rsum += (f0.x + f0.y) + (f1.x + f1.y) + (f2.x + f2.y) + (f3.x + f3.y);
            *(float4*)&srow[j0]     = make_float4(f0.x, f0.y, f1.x, f1.y);
            *(float4*)&srow[j0 + 4] = make_float4(f2.x, f2.y, f3.x, f3.y);
            uint4 pk;
            pk.x = *(unsigned*)&b0; pk.y = *(unsigned*)&b1;
            pk.z = *(unsigned*)&b2; pk.w = *(unsigned*)&b3;
            *(uint4*)&g_Eh[goff + j0] = pk;
        }
        atomicAdd(&g_rs[n][l0 + r], rsum);
    }
    __syncthreads();
    // Phase B: col sums (lanes read consecutive cols -> conflict-free)
    if (tid < 128) {
        float s0 = 0.0f, s1 = 0.0f, s2 = 0.0f, s3 = 0.0f;
        #pragma unroll 8
        for (int r = 0; r < 128; r += 4) {
            s0 += stage[(r + 0) * 136 + tid];
            s1 += stage[(r + 1) * 136 + tid];
            s2 += stage[(r + 2) * 136 + tid];
            s3 += stage[(r + 3) * 136 + tid];
        }
        atomicAdd(&g_cs[n][m0 + tid], (s0 + s1) + (s2 + s3));
    }
}

// ---------------- kernel 3.5: invert stats once ----------------
__global__ void invert_stats() {
    int i = blockIdx.x * blockDim.x + threadIdx.x;
    if (i < kNB * kL) {
        (&g_rs[0][0])[i] = 1.0f / (&g_rs[0][0])[i];
        (&g_cs[0][0])[i] = 1.0f / (&g_cs[0][0])[i];
    }
}

// ---------------- kernel 4: v projection (fp16 wmma) + fused bias/softmax-scale/bf16 ----------------
__global__ void __launch_bounds__(256) proj_v(const float* __restrict__ x1,
                                              const float* __restrict__ x2) {
    const int side = blockIdx.z >> 1;
    const int n    = blockIdx.z & 1;
    const float* x = (side ? x2 : x1) + (size_t)n * kC * kL;
    const int n0 = blockIdx.x * 256;
    const int c0 = blockIdx.y * 128;

    __shared__ __align__(16) __half As[128 * 40];   // [d-row][k], LD 40
    __shared__ __align__(16) __half Bs[32 * 264];   // [k][l], LD 264

    const int tid = threadIdx.x;
    const int warp = tid >> 5, lane = tid & 31;
    const int wm = warp & 1, wn = warp >> 1;

    wmma::fragment<wmma::accumulator, 16, 16, 16, float> acc[4][4];
    #pragma unroll
    for (int mi = 0; mi < 4; mi++)
        #pragma unroll
        for (int ni = 0; ni < 4; ni++)
            wmma::fill_fragment(acc[mi][ni], 0.0f);

    for (int kb = 0; kb < kC; kb += 32) {
        __syncthreads();
        #pragma unroll
        for (int it = 0; it < 2; it++) {
            int idx = tid + it * 256;
            int row = idx >> 2, q8 = (idx & 3) << 3;
            *(uint4*)&As[row * 40 + q8] = *(const uint4*)&g_Wvh[side][c0 + row][kb + q8];
        }
        {
            int k = tid >> 3, j0 = (tid & 7) << 5;
            const float* xs = &x[(size_t)(kb + k) * kL + n0 + j0];
            #pragma unroll
            for (int s = 0; s < 4; s++) {
                float4 f0 = *(const float4*)&xs[s * 8];
                float4 f1 = *(const float4*)&xs[s * 8 + 4];
                __half2 h0 = __floats2half2_rn(f0.x, f0.y);
                __half2 h1 = __floats2half2_rn(f0.z, f0.w);
                __half2 h2 = __floats2half2_rn(f1.x, f1.y);
                __half2 h3 = __floats2half2_rn(f1.z, f1.w);
                uint4 u;
                u.x = *(unsigned*)&h0; u.y = *(unsigned*)&h1;
                u.z = *(unsigned*)&h2; u.w = *(unsigned*)&h3;
                *(uint4*)&Bs[k * 264 + j0 + s * 8] = u;
            }
        }
        __syncthreads();
        #pragma unroll
        for (int kk = 0; kk < 2; kk++) {
            wmma::fragment<wmma::matrix_a, 16, 16, 16, __half, wmma::row_major> af[4];
            wmma::fragment<wmma::matrix_b, 16, 16, 16, __half, wmma::row_major> bf[4];
            #pragma unroll
            for (int mi = 0; mi < 4; mi++)
                wmma::load_matrix_sync(af[mi], As + (wm * 64 + mi * 16) * 40 + kk * 16, 40);
            #pragma unroll
            for (int ni = 0; ni < 4; ni++)
                wmma::load_matrix_sync(bf[ni], Bs + (kk * 16) * 264 + wn * 64 + ni * 16, 264);
            #pragma unroll
            for (int mi = 0; mi < 4; mi++)
                #pragma unroll
                for (int ni = 0; ni < 4; ni++)
                    wmma::mma_sync(acc[mi][ni], af[mi], bf[ni], acc[mi][ni]);
        }
    }

    __syncthreads();
    float* stage = (float*)As + warp * 320;  // 16x20 per warp, aliases As
    const float* inv = (side == 0) ? g_rs[n] : g_cs[n];
    #pragma unroll
    for (int mi = 0; mi < 4; mi++) {
        #pragma unroll
        for (int ni = 0; ni < 4; ni++) {
            wmma::store_matrix_sync(stage, acc[mi][ni], 20, wmma::mem_row_major);
            __syncwarp();
            #pragma unroll
            for (int t = 0; t < 8; t++) {
                int idx = lane * 8 + t;
                int r = idx >> 4, cc = idx & 15;
                int d = c0 + wm * 64 + mi * 16 + r;
                int l = n0 + wn * 64 + ni * 16 + cc;
                float v = (stage[r * 20 + cc] + g_bp[side][kCK + d]) * inv[l];
                g_vh[side][n][d][l] = __float2bfloat16_rn(v);
            }
            __syncwarp();
        }
    }
}

// ---------------- kernel 5: out = x + Vscaled @ E(^T), bf16 wmma, 4-stage cp.async ----------------
// OCCUPANCY EXPERIMENT: CTA tile M=128(c) x N=128(pos), 80KB smem -> 2 CTAs/SM,
// grid 256 blocks = one wave at occ 2 = 4 warps/SMSP (was 2). Warp tile 64x32 (2x4 warps).
// TRANS=0: B[k=l][n=m] = E[l][m] -> row-major tile 32x128, LD 136
// TRANS=1: B[k=m][n=l] = E[l][m] -> col-major tile 128x32, LD 40
constexpr int kALDh   = 40;
constexpr int kBLDh0  = 136;
constexpr int kAOffB  = 128 * kALDh * 2;            // 10240 B
constexpr int kStgB   = kAOffB + 128 * kALDh * 2;   // 20480 B per stage (B: max(32*136, 128*40)*2)
constexpr int kNStg   = 4;
constexpr int kAttnSmem = kNStg * kStgB;            // 81920 B -> 2 CTAs/SM

template <int TRANS>
__device__ __forceinline__ void run_attn(char* smem, const float* __restrict__ x,
                                         float* __restrict__ o) {
    const int n  = blockIdx.z & 1;
    const int c0 = blockIdx.y * 128;
    const int p0 = blockIdx.x * 128;
    const int tid = threadIdx.x;
    const int warp = tid >> 5, lane = tid & 31;
    const int wm = warp & 1, wn = warp >> 1;

    const __nv_bfloat16* A  = &g_vh[TRANS][n][0][0];
    const __nv_bfloat16* Eb = g_Eh + (size_t)n * kL * kL;

    auto issue = [&](int s, int kb) {
        __nv_bfloat16* As = (__nv_bfloat16*)(smem + s * kStgB);
        __nv_bfloat16* Bs = (__nv_bfloat16*)(smem + s * kStgB + kAOffB);
        #pragma unroll
        for (int it = 0; it < 2; it++) {   // A: 128 rows x 32k = 512 cp16
            int idx = tid + it * 256;
            int row = idx >> 2, q = (idx & 3) << 3;
            cp_async16(As + row * kALDh + q, A + (size_t)(c0 + row) * kL + kb + q);
        }
        if (TRANS == 0) {
            #pragma unroll
            for (int it = 0; it < 2; it++) {   // B: 32 rows x 128 = 512 cp16
                int idx = tid + it * 256;
                int k = idx >> 4, q = (idx & 15) << 3;
                cp_async16(Bs + k * kBLDh0 + q, Eb + (size_t)(kb + k) * kL + p0 + q);
            }
        } else {
            #pragma unroll
            for (int it = 0; it < 2; it++) {   // B: 128 rows x 32 = 512 cp16
                int idx = tid + it * 256;
                int row = idx >> 2, q = (idx & 3) << 3;
                cp_async16(Bs + row * kALDh + q, Eb + (size_t)(p0 + row) * kL + kb + q);
            }
        }
    };

    wmma::fragment<wmma::accumulator, 16, 16, 16, float> acc[4][2];
    #pragma unroll
    for (int mi = 0; mi < 4; mi++)
        #pragma unroll
        for (int ni = 0; ni < 2; ni++)
            wmma::fill_fragment(acc[mi][ni], 0.0f);

    constexpr int NCH = kL / 32;  // 128
    issue(0, 0);  CP_ASYNC_COMMIT();
    issue(1, 32); CP_ASYNC_COMMIT();
    issue(2, 64); CP_ASYNC_COMMIT();

    for (int chunk = 0; chunk < NCH; chunk++) {
        CP_ASYNC_WAIT2();
        __syncthreads();
        int pre = chunk + 3;
        if (pre < NCH) issue(pre & 3, pre * 32);
        CP_ASYNC_COMMIT();

        const __nv_bfloat16* As = (const __nv_bfloat16*)(smem + (chunk & 3) * kStgB);
        const __nv_bfloat16* Bs = (const __nv_bfloat16*)(smem + (chunk & 3) * kStgB + kAOffB);
        #pragma unroll
        for (int kk = 0; kk < 2; kk++) {
            wmma::fragment<wmma::matrix_a, 16, 16, 16, __nv_bfloat16, wmma::row_major> af[4];
            #pragma unroll
            for (int mi = 0; mi < 4; mi++)
                wmma::load_matrix_sync(af[mi], As + (wm * 64 + mi * 16) * kALDh + kk * 16, kALDh);
            if (TRANS == 0) {
                wmma::fragment<wmma::matrix_b, 16, 16, 16, __nv_bfloat16, wmma::row_major> bf[2];
                #pragma unroll
                for (int ni = 0; ni < 2; ni++)
                    wmma::load_matrix_sync(bf[ni], Bs + (kk * 16) * kBLDh0 + wn * 32 + ni * 16, kBLDh0);
                #pragma unroll
                for (int mi = 0; mi < 4; mi++)
                    #pragma unroll
                    for (int ni = 0; ni < 2; ni++)
                        wmma::mma_sync(acc[mi][ni], af[mi], bf[ni], acc[mi][ni]);
            } else {
                wmma::fragment<wmma::matrix_b, 16, 16, 16, __nv_bfloat16, wmma::col_major> bf[2];
                #pragma unroll
                for (int ni = 0; ni < 2; ni++)
                    wmma::load_matrix_sync(bf[ni], Bs + (wn * 32 + ni * 16) * kALDh + kk * 16, kALDh);
                #pragma unroll
                for (int mi = 0; mi < 4; mi++)
                    #pragma unroll
                    for (int ni = 0; ni < 2; ni++)
                        wmma::mma_sync(acc[mi][ni], af[mi], bf[ni], acc[mi][ni]);
            }
        }
    }

    // epilogue: stage frags through smem, add residual, write
    __syncthreads();
    float* stage = (float*)smem + warp * 320;  // 16x20 per warp, warp-private
    #pragma unroll
    for (int mi = 0; mi < 4; mi++) {
        #pragma unroll
        for (int ni = 0; ni < 2; ni++) {
            wmma::store_matrix_sync(stage, acc[mi][ni], 20, wmma::mem_row_major);
            __syncwarp();
            #pragma unroll
            for (int t = 0; t < 8; t++) {
                int idx = lane * 8 + t;
                int r = idx >> 4, cc = idx & 15;
                int orow = c0 + wm * 64 + mi * 16 + r;
                int ocol = p0 + wn * 32 + ni * 16 + cc;
                size_t g = ((size_t)n * kC + orow) * kL + ocol;
                o[g] = x[g] + stage[r * 20 + cc];
            }
            __syncwarp();
        }
    }
}

__global__ void __launch_bounds__(256) attn_gemm2(const float* __restrict__ x1,
                                                  const float* __restrict__ x2,
                                                  float* __restrict__ out,
                                                  size_t half) {
    extern __shared__ char asmem[];
    const int trans = blockIdx.z >> 1;
    if (trans == 0) run_attn<0>(asmem, x1, out);
    else            run_attn<1>(asmem, x2, out + half);
}

// ---------------- launch ----------------
extern "C" void kernel_launch(void* const* d_in, const int* in_sizes, int n_in,
                              void* d_out, int out_size) {
    const float* x1  = (const float*)d_in[0];
    const float* x2  = (const float*)d_in[1];
    const float* Wk1 = (const float*)d_in[2];
    const float* bk1 = (const float*)d_in[3];
    const float* Wk2 = (const float*)d_in[4];
    const float* bk2 = (const float*)d_in[5];
    const float* Wv1 = (const float*)d_in[6];
    const float* bv1 = (const float*)d_in[7];
    const float* Wv2 = (const float*)d_in[8];
    const float* bv2 = (const float*)d_in[9];
    float* out = (float*)d_out;
    const size_t half = (size_t)out_size / 2;  // out1 | out2

    static bool attr_done = false;
    if (!attr_done) {
        cudaFuncSetAttribute(cor_kernel, cudaFuncAttributeMaxDynamicSharedMemorySize, kCorSmemBytes);
        cudaFuncSetAttribute(attn_gemm2, cudaFuncAttributeMaxDynamicSharedMemorySize, kAttnSmem);
        attr_done = true;
    }

    pack_w<<<(kD * kC + 255) / 256, 256>>>(Wk1, bk1, Wk2, bk2, Wv1, bv1, Wv2, bv2);
    zero_stats<<<(kNB * kL + 255) / 256, 256>>>();
    proj_k<<<dim3(kL / 128, 1, 4), 256>>>(x1, x2);
    cor_kernel<<<dim3(kL / 128, kL / 128, kNB), 256, kCorSmemBytes>>>();
    invert_stats<<<(kNB * kL + 255) / 256, 256>>>();
    proj_v<<<dim3(kL / 256, kC / 128, 4), 256>>>(x1, x2);
    attn_gemm2<<<dim3(kL / 128, kC / 128, 4), 256, kAttnSmem>>>(x1, x2, out, half);
}

// round 17
// speedup vs baseline: 1.0876x; 1.0876x over previous
#include <cuda_runtime.h>
#include <cuda_bf16.h>
#include <cuda_fp16.h>
#include <mma.h>

using namespace nvcuda;

constexpr int kNB = 2;     // batch
constexpr int kC  = 256;   // channels
constexpr int kCK = 32;    // key channels
constexpr int kL  = 4096;  // T*H*W
constexpr int kD  = 288;   // stacked output channels (32 k + 256 v)

// ---------------- scratch (static __device__ — no allocations allowed) ----------------
__device__ float g_Wp[2][kD][kC];            // packed weights per side (fp32, k-proj uses rows 0..31)
__device__ float g_bp[2][kD];                // packed bias per side
__device__ __half g_Wvh[2][kC][kC];          // v-weights fp16 [d][c]
__device__ float g_k[2][kNB][kCK][kL];       // k1 (side 0), k2 (side 1)
__device__ __nv_bfloat16 g_vh[2][kNB][kC][kL];        // scaled v, bf16 (written by proj_v epilogue)
__device__ __nv_bfloat16 g_Eh[(size_t)kNB * kL * kL]; // exp(cor), bf16 (64 MB)
__device__ float g_rs[kNB][kL];              // row sums of E -> inverted in place
__device__ float g_cs[kNB][kL];              // col sums of E -> inverted in place

// FFMA-only exp (avoids MUFU bottleneck: ~33M evals)
__device__ __forceinline__ float fast_exp(float x) {
    x = fminf(fmaxf(x, -80.0f), 80.0f);
    float y = x * 1.44269504088896341f;  // x * log2(e)
    float n = rintf(y);
    float f = y - n;
    float p =        1.3333558e-3f;
    p = fmaf(p, f,   9.6181291e-3f);
    p = fmaf(p, f,   5.5504110e-2f);
    p = fmaf(p, f,   2.4022652e-1f);
    p = fmaf(p, f,   6.9314718e-1f);
    p = fmaf(p, f,   1.0f);
    float s = __int_as_float(((int)n + 127) << 23);
    return p * s;
}

__device__ __forceinline__ void cp_async16(void* sdst, const void* gsrc) {
    unsigned saddr = (unsigned)__cvta_generic_to_shared(sdst);
    asm volatile("cp.async.cg.shared.global [%0], [%1], 16;\n" :: "r"(saddr), "l"(gsrc));
}
#define CP_ASYNC_COMMIT() asm volatile("cp.async.commit_group;\n" ::: "memory")
#define CP_ASYNC_WAIT2()  asm volatile("cp.async.wait_group 2;\n" ::: "memory")

// ---------------- kernel 1: pack weights + fp16 v-weights + zero stats ----------------
__global__ void pack_w(const float* __restrict__ Wk1, const float* __restrict__ bk1,
                       const float* __restrict__ Wk2, const float* __restrict__ bk2,
                       const float* __restrict__ Wv1, const float* __restrict__ bv1,
                       const float* __restrict__ Wv2, const float* __restrict__ bv2) {
    int i = blockIdx.x * blockDim.x + threadIdx.x;
    if (i < kD * kC) {
        int d = i / kC, c = i % kC;
        g_Wp[0][d][c] = (d < kCK) ? Wk1[d * kC + c] : Wv1[(d - kCK) * kC + c];
        g_Wp[1][d][c] = (d < kCK) ? Wk2[d * kC + c] : Wv2[(d - kCK) * kC + c];
    }
    if (i < kC * kC) {
        int d = i >> 8, c = i & 255;
        g_Wvh[0][d][c] = __float2half_rn(Wv1[i]);
        g_Wvh[1][d][c] = __float2half_rn(Wv2[i]);
    }
    if (i < kD) {
        g_bp[0][i] = (i < kCK) ? bk1[i] : bv1[i - kCK];
        g_bp[1][i] = (i < kCK) ? bk2[i] : bv2[i - kCK];
    }
    if (i < kNB * kL) {
        (&g_rs[0][0])[i] = 0.0f;
        (&g_cs[0][0])[i] = 0.0f;
    }
}

// ---------------- kernel 2a: k projection (fp32 SIMT, tiny: 0.27 GF) ----------------
__global__ void __launch_bounds__(256) proj_k(const float* __restrict__ x1,
                                              const float* __restrict__ x2) {
    const int side = blockIdx.z >> 1;
    const int n    = blockIdx.z & 1;
    const float* x = (side ? x2 : x1) + (size_t)n * kC * kL;
    const int l0 = blockIdx.x * 128;

    __shared__ float Ws[256][32];   // [k][d]
    __shared__ float Xs[16][128];

    const int tid = threadIdx.x;
    const int d  = tid & 31;
    const int lg = tid >> 5;

    for (int i = tid; i < 256 * 32; i += 256) {
        int k = i >> 5, dd = i & 31;
        Ws[k][dd] = g_Wp[side][dd][k];
    }

    float acc[16] = {};
    for (int kb = 0; kb < kC; kb += 16) {
        __syncthreads();
        for (int i = tid; i < 512; i += 256) {
            int k = i >> 5, g4 = (i & 31) << 2;
            *(float4*)&Xs[k][g4] = *(const float4*)&x[(size_t)(kb + k) * kL + l0 + g4];
        }
        __syncthreads();
        #pragma unroll
        for (int k = 0; k < 16; k++) {
            float w = Ws[kb + k][d];
            float4 v0 = *(float4*)&Xs[k][lg * 16];
            float4 v1 = *(float4*)&Xs[k][lg * 16 + 4];
            float4 v2 = *(float4*)&Xs[k][lg * 16 + 8];
            float4 v3 = *(float4*)&Xs[k][lg * 16 + 12];
            acc[0]  = fmaf(w, v0.x, acc[0]);  acc[1]  = fmaf(w, v0.y, acc[1]);
            acc[2]  = fmaf(w, v0.z, acc[2]);  acc[3]  = fmaf(w, v0.w, acc[3]);
            acc[4]  = fmaf(w, v1.x, acc[4]);  acc[5]  = fmaf(w, v1.y, acc[5]);
            acc[6]  = fmaf(w, v1.z, acc[6]);  acc[7]  = fmaf(w, v1.w, acc[7]);
            acc[8]  = fmaf(w, v2.x, acc[8]);  acc[9]  = fmaf(w, v2.y, acc[9]);
            acc[10] = fmaf(w, v2.z, acc[10]); acc[11] = fmaf(w, v2.w, acc[11]);
            acc[12] = fmaf(w, v3.x, acc[12]); acc[13] = fmaf(w, v3.y, acc[13]);
            acc[14] = fmaf(w, v3.z, acc[14]); acc[15] = fmaf(w, v3.w, acc[15]);
        }
    }
    float bias = g_bp[side][d];
    #pragma unroll
    for (int j = 0; j < 16; j++)
        g_k[side][n][d][l0 + lg * 16 + j] = acc[j] + bias;
}

// ---------------- kernel 3: cor = k1^T k2 via fp16 wmma, E=bf16(exp), fused sums ----------------
constexpr int kCorSmemBytes = 128 * 136 * 4;  // 69632 (stage dominates; half tiles overlap)

__global__ void __launch_bounds__(256) cor_kernel() {
    extern __shared__ float csm[];
    __half* hA = (__half*)csm;            // 32 x 136 halves ([k][l])
    __half* hB = hA + 32 * 136;           // 32 x 136 halves ([k][m])
    float* stage = csm;                   // 128 x 136 fp32, reused after mma

    const int n  = blockIdx.z;
    const int l0 = blockIdx.y * 128;
    const int m0 = blockIdx.x * 128;
    const int tid = threadIdx.x;
    const int warp = tid >> 5;
    const int wm = warp & 1, wn = warp >> 1;

    const float* k1 = &g_k[0][n][0][0];
    const float* k2 = &g_k[1][n][0][0];

    for (int i4 = tid; i4 < 1024; i4 += 256) {
        int k = i4 >> 5, j4 = (i4 & 31) << 2;
        float4 a = *(const float4*)&k1[(size_t)k * kL + l0 + j4];
        float4 b = *(const float4*)&k2[(size_t)k * kL + m0 + j4];
        __half2 a0 = __floats2half2_rn(a.x, a.y), a1 = __floats2half2_rn(a.z, a.w);
        __half2 b0 = __floats2half2_rn(b.x, b.y), b1 = __floats2half2_rn(b.z, b.w);
        uint2 ua, ub;
        ua.x = *(unsigned*)&a0; ua.y = *(unsigned*)&a1;
        ub.x = *(unsigned*)&b0; ub.y = *(unsigned*)&b1;
        *(uint2*)&hA[k * 136 + j4] = ua;
        *(uint2*)&hB[k * 136 + j4] = ub;
    }
    __syncthreads();

    wmma::fragment<wmma::accumulator, 16, 16, 16, float> acc[4][2];
    #pragma unroll
    for (int mi = 0; mi < 4; mi++)
        #pragma unroll
        for (int ni = 0; ni < 2; ni++)
            wmma::fill_fragment(acc[mi][ni], 0.0f);

    #pragma unroll
    for (int kk = 0; kk < 2; kk++) {
        wmma::fragment<wmma::matrix_a, 16, 16, 16, __half, wmma::col_major> af[4];
        wmma::fragment<wmma::matrix_b, 16, 16, 16, __half, wmma::row_major> bf[2];
        #pragma unroll
        for (int mi = 0; mi < 4; mi++)
            wmma::load_matrix_sync(af[mi], hA + (kk * 16) * 136 + wm * 64 + mi * 16, 136);
        #pragma unroll
        for (int ni = 0; ni < 2; ni++)
            wmma::load_matrix_sync(bf[ni], hB + (kk * 16) * 136 + wn * 32 + ni * 16, 136);
        #pragma unroll
        for (int mi = 0; mi < 4; mi++)
            #pragma unroll
            for (int ni = 0; ni < 2; ni++)
                wmma::mma_sync(acc[mi][ni], af[mi], bf[ni], acc[mi][ni]);
    }

    __syncthreads();  // done reading tiles; stage overwrites them
    #pragma unroll
    for (int mi = 0; mi < 4; mi++)
        #pragma unroll
        for (int ni = 0; ni < 2; ni++)
            wmma::store_matrix_sync(stage + (wm * 64 + mi * 16) * 136 + wn * 32 + ni * 16,
                                    acc[mi][ni], 136, wmma::mem_row_major);
    __syncthreads();

    // Phase A: exp + bf16 write + row sums; exp'd values written back to stage
    {
        const int r  = tid >> 1;
        const int ch = (tid & 1) << 6;  // 0 or 64
        float* srow = stage + r * 136 + ch;
        float rsum = 0.0f;
        size_t goff = (size_t)n * kL * kL + (size_t)(l0 + r) * kL + m0 + ch;
        #pragma unroll
        for (int j0 = 0; j0 < 64; j0 += 8) {
            float4 v0 = *(float4*)&srow[j0];
            float4 v1 = *(float4*)&srow[j0 + 4];
            __nv_bfloat162 b0 = __floats2bfloat162_rn(fast_exp(v0.x), fast_exp(v0.y));
            __nv_bfloat162 b1 = __floats2bfloat162_rn(fast_exp(v0.z), fast_exp(v0.w));
            __nv_bfloat162 b2 = __floats2bfloat162_rn(fast_exp(v1.x), fast_exp(v1.y));
            __nv_bfloat162 b3 = __floats2bfloat162_rn(fast_exp(v1.z), fast_exp(v1.w));
            float2 f0 = __bfloat1622float2(b0), f1 = __bfloat1622float2(b1);
            float2 f2 = __bfloat1622float2(b2), f3 = __bfloat1622float2(b3);
            rsum += (f0.x + f0.y) + (f1.x + f1.y) + (f2.x + f2.y) + (f3.x + f3.y);
            *(float4*)&srow[j0]     = make_float4(f0.x, f0.y, f1.x, f1.y);
            *(float4*)&srow[j0 + 4] = make_float4(f2.x, f2.y, f3.x, f3.y);
            uint4 pk;
            pk.x = *(unsigned*)&b0; pk.y = *(unsigned*)&b1;
            pk.z = *(unsigned*)&b2; pk.w = *(unsigned*)&b3;
            *(uint4*)&g_Eh[goff + j0] = pk;
        }
        atomicAdd(&g_rs[n][l0 + r], rsum);
    }
    __syncthreads();
    // Phase B: col sums (lanes read consecutive cols -> conflict-free)
    if (tid < 128) {
        float s0 = 0.0f, s1 = 0.0f, s2 = 0.0f, s3 = 0.0f;
        #pragma unroll 8
        for (int r = 0; r < 128; r += 4) {
            s0 += stage[(r + 0) * 136 + tid];
            s1 += stage[(r + 1) * 136 + tid];
            s2 += stage[(r + 2) * 136 + tid];
            s3 += stage[(r + 3) * 136 + tid];
        }
        atomicAdd(&g_cs[n][m0 + tid], (s0 + s1) + (s2 + s3));
    }
}

// ---------------- kernel 3.5: invert stats once ----------------
__global__ void invert_stats() {
    int i = blockIdx.x * blockDim.x + threadIdx.x;
    if (i < kNB * kL) {
        (&g_rs[0][0])[i] = 1.0f / (&g_rs[0][0])[i];
        (&g_cs[0][0])[i] = 1.0f / (&g_cs[0][0])[i];
    }
}

// ---------------- kernel 4: v projection (fp16 wmma) + fused bias/softmax-scale/bf16 ----------------
__global__ void __launch_bounds__(256) proj_v(const float* __restrict__ x1,
                                              const float* __restrict__ x2) {
    const int side = blockIdx.z >> 1;
    const int n    = blockIdx.z & 1;
    const float* x = (side ? x2 : x1) + (size_t)n * kC * kL;
    const int n0 = blockIdx.x * 256;
    const int c0 = blockIdx.y * 128;

    __shared__ __align__(16) __half As[128 * 40];   // [d-row][k], LD 40
    __shared__ __align__(16) __half Bs[32 * 264];   // [k][l], LD 264

    const int tid = threadIdx.x;
    const int warp = tid >> 5, lane = tid & 31;
    const int wm = warp & 1, wn = warp >> 1;

    wmma::fragment<wmma::accumulator, 16, 16, 16, float> acc[4][4];
    #pragma unroll
    for (int mi = 0; mi < 4; mi++)
        #pragma unroll
        for (int ni = 0; ni < 4; ni++)
            wmma::fill_fragment(acc[mi][ni], 0.0f);

    for (int kb = 0; kb < kC; kb += 32) {
        __syncthreads();
        #pragma unroll
        for (int it = 0; it < 2; it++) {
            int idx = tid + it * 256;
            int row = idx >> 2, q8 = (idx & 3) << 3;
            *(uint4*)&As[row * 40 + q8] = *(const uint4*)&g_Wvh[side][c0 + row][kb + q8];
        }
        {
            int k = tid >> 3, j0 = (tid & 7) << 5;
            const float* xs = &x[(size_t)(kb + k) * kL + n0 + j0];
            #pragma unroll
            for (int s = 0; s < 4; s++) {
                float4 f0 = *(const float4*)&xs[s * 8];
                float4 f1 = *(const float4*)&xs[s * 8 + 4];
                __half2 h0 = __floats2half2_rn(f0.x, f0.y);
                __half2 h1 = __floats2half2_rn(f0.z, f0.w);
                __half2 h2 = __floats2half2_rn(f1.x, f1.y);
                __half2 h3 = __floats2half2_rn(f1.z, f1.w);
                uint4 u;
                u.x = *(unsigned*)&h0; u.y = *(unsigned*)&h1;
                u.z = *(unsigned*)&h2; u.w = *(unsigned*)&h3;
                *(uint4*)&Bs[k * 264 + j0 + s * 8] = u;
            }
        }
        __syncthreads();
        #pragma unroll
        for (int kk = 0; kk < 2; kk++) {
            wmma::fragment<wmma::matrix_a, 16, 16, 16, __half, wmma::row_major> af[4];
            wmma::fragment<wmma::matrix_b, 16, 16, 16, __half, wmma::row_major> bf[4];
            #pragma unroll
            for (int mi = 0; mi < 4; mi++)
                wmma::load_matrix_sync(af[mi], As + (wm * 64 + mi * 16) * 40 + kk * 16, 40);
            #pragma unroll
            for (int ni = 0; ni < 4; ni++)
                wmma::load_matrix_sync(bf[ni], Bs + (kk * 16) * 264 + wn * 64 + ni * 16, 264);
            #pragma unroll
            for (int mi = 0; mi < 4; mi++)
                #pragma unroll
                for (int ni = 0; ni < 4; ni++)
                    wmma::mma_sync(acc[mi][ni], af[mi], bf[ni], acc[mi][ni]);
        }
    }

    __syncthreads();
    float* stage = (float*)As + warp * 320;  // 16x20 per warp, aliases As
    const float* inv = (side == 0) ? g_rs[n] : g_cs[n];
    #pragma unroll
    for (int mi = 0; mi < 4; mi++) {
        #pragma unroll
        for (int ni = 0; ni < 4; ni++) {
            wmma::store_matrix_sync(stage, acc[mi][ni], 20, wmma::mem_row_major);
            __syncwarp();
            #pragma unroll
            for (int t = 0; t < 8; t++) {
                int idx = lane * 8 + t;
                int r = idx >> 4, cc = idx & 15;
                int d = c0 + wm * 64 + mi * 16 + r;
                int l = n0 + wn * 64 + ni * 16 + cc;
                float v = (stage[r * 20 + cc] + g_bp[side][kCK + d]) * inv[l];
                g_vh[side][n][d][l] = __float2bfloat16_rn(v);
            }
            __syncwarp();
        }
    }
}

// ---------------- kernel 5: out = x + Vscaled @ E(^T), bf16 wmma, 4-stage cp.async ----------------
// R12 config (best): CTA tile M=128(c) x N=256(pos), Kc=32 (2 kk of 16). 8 warps (2x4),
// warp tile 64x64. Grid 128 CTAs, occ 1 — at the legacy-HMMA pipe ceiling.
// TRANS=0: B[k=l][n=m] = E[l][m] -> row-major tile 32x256, LD 264
// TRANS=1: B[k=m][n=l] = E[l][m] -> col-major tile 256x32, LD 40
constexpr int kALDh   = 40;
constexpr int kBLDh0  = 264;
constexpr int kAOffB  = 128 * kALDh * 2;            // 10240 B
constexpr int kStgB   = kAOffB + 256 * kALDh * 2;   // 30720 B per stage
constexpr int kNStg   = 4;
constexpr int kAttnSmem = kNStg * kStgB;            // 122880 B

template <int TRANS>
__device__ __forceinline__ void run_attn(char* smem, const float* __restrict__ x,
                                         float* __restrict__ o) {
    const int n  = blockIdx.z & 1;
    const int c0 = blockIdx.y * 128;
    const int p0 = blockIdx.x * 256;
    const int tid = threadIdx.x;
    const int warp = tid >> 5, lane = tid & 31;
    const int wm = warp & 1, wn = warp >> 1;

    const __nv_bfloat16* A  = &g_vh[TRANS][n][0][0];
    const __nv_bfloat16* Eb = g_Eh + (size_t)n * kL * kL;

    auto issue = [&](int s, int kb) {
        __nv_bfloat16* As = (__nv_bfloat16*)(smem + s * kStgB);
        __nv_bfloat16* Bs = (__nv_bfloat16*)(smem + s * kStgB + kAOffB);
        #pragma unroll
        for (int it = 0; it < 2; it++) {
            int idx = tid + it * 256;
            int row = idx >> 2, q = (idx & 3) << 3;
            cp_async16(As + row * kALDh + q, A + (size_t)(c0 + row) * kL + kb + q);
        }
        if (TRANS == 0) {
            #pragma unroll
            for (int it = 0; it < 4; it++) {
                int idx = tid + it * 256;
                int k = idx >> 5, q = (idx & 31) << 3;
                cp_async16(Bs + k * kBLDh0 + q, Eb + (size_t)(kb + k) * kL + p0 + q);
            }
        } else {
            #pragma unroll
            for (int it = 0; it < 4; it++) {
                int idx = tid + it * 256;
                int row = idx >> 2, q = (idx & 3) << 3;
                cp_async16(Bs + row * kALDh + q, Eb + (size_t)(p0 + row) * kL + kb + q);
            }
        }
    };

    wmma::fragment<wmma::accumulator, 16, 16, 16, float> acc[4][4];
    #pragma unroll
    for (int mi = 0; mi < 4; mi++)
        #pragma unroll
        for (int ni = 0; ni < 4; ni++)
            wmma::fill_fragment(acc[mi][ni], 0.0f);

    constexpr int NCH = kL / 32;  // 128
    issue(0, 0);  CP_ASYNC_COMMIT();
    issue(1, 32); CP_ASYNC_COMMIT();
    issue(2, 64); CP_ASYNC_COMMIT();

    for (int chunk = 0; chunk < NCH; chunk++) {
        CP_ASYNC_WAIT2();
        __syncthreads();
        int pre = chunk + 3;
        if (pre < NCH) issue(pre & 3, pre * 32);
        CP_ASYNC_COMMIT();

        const __nv_bfloat16* As = (const __nv_bfloat16*)(smem + (chunk & 3) * kStgB);
        const __nv_bfloat16* Bs = (const __nv_bfloat16*)(smem + (chunk & 3) * kStgB + kAOffB);
        #pragma unroll
        for (int kk = 0; kk < 2; kk++) {
            wmma::fragment<wmma::matrix_a, 16, 16, 16, __nv_bfloat16, wmma::row_major> af[4];
            #pragma unroll
            for (int mi = 0; mi < 4; mi++)
                wmma::load_matrix_sync(af[mi], As + (wm * 64 + mi * 16) * kALDh + kk * 16, kALDh);
            if (TRANS == 0) {
                wmma::fragment<wmma::matrix_b, 16, 16, 16, __nv_bfloat16, wmma::row_major> bf[4];
                #pragma unroll
                for (int ni = 0; ni < 4; ni++)
                    wmma::load_matrix_sync(bf[ni], Bs + (kk * 16) * kBLDh0 + wn * 64 + ni * 16, kBLDh0);
                #pragma unroll
                for (int mi = 0; mi < 4; mi++)
                    #pragma unroll
                    for (int ni = 0; ni < 4; ni++)
                        wmma::mma_sync(acc[mi][ni], af[mi], bf[ni], acc[mi][ni]);
            } else {
                wmma::fragment<wmma::matrix_b, 16, 16, 16, __nv_bfloat16, wmma::col_major> bf[4];
                #pragma unroll
                for (int ni = 0; ni < 4; ni++)
                    wmma::load_matrix_sync(bf[ni], Bs + (wn * 64 + ni * 16) * kALDh + kk * 16, kALDh);
                #pragma unroll
                for (int mi = 0; mi < 4; mi++)
                    #pragma unroll
                    for (int ni = 0; ni < 4; ni++)
                        wmma::mma_sync(acc[mi][ni], af[mi], bf[ni], acc[mi][ni]);
            }
        }
    }

    // epilogue: stage frags through smem, add residual, write
    __syncthreads();
    float* stage = (float*)smem + warp * 320;  // 16x20 per warp, warp-private
    #pragma unroll
    for (int mi = 0; mi < 4; mi++) {
        #pragma unroll
        for (int ni = 0; ni < 4; ni++) {
            wmma::store_matrix_sync(stage, acc[mi][ni], 20, wmma::mem_row_major);
            __syncwarp();
            #pragma unroll
            for (int t = 0; t < 8; t++) {
                int idx = lane * 8 + t;
                int r = idx >> 4, cc = idx & 15;
                int orow = c0 + wm * 64 + mi * 16 + r;
                int ocol = p0 + wn * 64 + ni * 16 + cc;
                size_t g = ((size_t)n * kC + orow) * kL + ocol;
                o[g] = x[g] + stage[r * 20 + cc];
            }
            __syncwarp();
        }
    }
}

__global__ void __launch_bounds__(256) attn_gemm2(const float* __restrict__ x1,
                                                  const float* __restrict__ x2,
                                                  float* __restrict__ out,
                                                  size_t half) {
    extern __shared__ char asmem[];
    const int trans = blockIdx.z >> 1;
    if (trans == 0) run_attn<0>(asmem, x1, out);
    else            run_attn<1>(asmem, x2, out + half);
}

// ---------------- launch ----------------
extern "C" void kernel_launch(void* const* d_in, const int* in_sizes, int n_in,
                              void* d_out, int out_size) {
    const float* x1  = (const float*)d_in[0];
    const float* x2  = (const float*)d_in[1];
    const float* Wk1 = (const float*)d_in[2];
    const float* bk1 = (const float*)d_in[3];
    const float* Wk2 = (const float*)d_in[4];
    const float* bk2 = (const float*)d_in[5];
    const float* Wv1 = (const float*)d_in[6];
    const float* bv1 = (const float*)d_in[7];
    const float* Wv2 = (const float*)d_in[8];
    const float* bv2 = (const float*)d_in[9];
    float* out = (float*)d_out;
    const size_t half = (size_t)out_size / 2;  // out1 | out2

    static bool attr_done = false;
    if (!attr_done) {
        cudaFuncSetAttribute(cor_kernel, cudaFuncAttributeMaxDynamicSharedMemorySize, kCorSmemBytes);
        // Request max shared carveout so 3 CTAs (3 x 69.6KB = 209KB) can co-reside:
        // the epilogue is issue/latency-bound at the current ~1.3 CTAs/SM.
        cudaFuncSetAttribute(cor_kernel, cudaFuncAttributePreferredSharedMemoryCarveout,
                             cudaSharedmemCarveoutMaxShared);
        cudaFuncSetAttribute(attn_gemm2, cudaFuncAttributeMaxDynamicSharedMemorySize, kAttnSmem);
        attr_done = true;
    }

    pack_w<<<(kD * kC + 255) / 256, 256>>>(Wk1, bk1, Wk2, bk2, Wv1, bv1, Wv2, bv2);
    proj_k<<<dim3(kL / 128, 1, 4), 256>>>(x1, x2);
    cor_kernel<<<dim3(kL / 128, kL / 128, kNB), 256, kCorSmemBytes>>>();
    invert_stats<<<(kNB * kL + 255) / 256, 256>>>();
    proj_v<<<dim3(kL / 256, kC / 128, 4), 256>>>(x1, x2);
    attn_gemm2<<<dim3(kL / 256, kC / 128, 4), 256, kAttnSmem>>>(x1, x2, out, half);
}